// round 15
// baseline (speedup 1.0000x reference)
#include <cuda_runtime.h>
#include <cstdint>

// CompetitiveSparse == elementwise: out = (f > 0.5f) ? 0.0f : f
// (win = max(excl_max, f) < f is identically false in the reference; the
// GEMM / sigmoid / top-k chain never influences the output.)
//
// R13: single-wave persistent grid. Previous optimum (2048 CTAs, 6 CTAs/SM
// resident on 152 SMs = 912 slots) ran 2.25 waves: ragged 224-CTA tail +
// 2 wave transitions. Here: 912 CTAs, grid-stride over the 2048 tiles
// (2-3 tiles each) -> one wave, imbalance granularity = 1 tile (~9 ns).
// Body unchanged from the verified optimum: VPT=8 batched LDG.128 via
// __ldcg + __stcs evict-first stores.

static constexpr float THRESHOLD = 0.5f;
static constexpr int VPT = 8;          // float4s per thread
static constexpr int THREADS = 256;
static constexpr int TILE = THREADS * VPT;   // 2048 float4s per tile
static constexpr int GRID = 912;             // 152 SMs * 6 resident CTAs

__device__ __forceinline__ float4 apply(float4 v) {
    v.x = (v.x > THRESHOLD) ? 0.0f : v.x;
    v.y = (v.y > THRESHOLD) ? 0.0f : v.y;
    v.z = (v.z > THRESHOLD) ? 0.0f : v.z;
    v.w = (v.w > THRESHOLD) ? 0.0f : v.w;
    return v;
}

__global__ void __launch_bounds__(THREADS)
competitive_sparse_kernel(const float4* __restrict__ f,
                          float4* __restrict__ out,
                          int n_tiles) {
    // Persistent: each CTA walks tiles blockIdx.x, +GRID, +2*GRID, ...
    for (int t = blockIdx.x; t < n_tiles; t += GRID) {
        int base = t * TILE + threadIdx.x;

        float4 v[VPT];
        #pragma unroll
        for (int k = 0; k < VPT; k++)
            v[k] = __ldcg(&f[base + k * THREADS]);     // 8 outstanding LDG.128

        #pragma unroll
        for (int k = 0; k < VPT; k++)
            __stcs(&out[base + k * THREADS], apply(v[k]));  // evict-first
    }
}

extern "C" void kernel_launch(void* const* d_in, const int* in_sizes, int n_in,
                              void* d_out, int out_size) {
    const float* features = (const float*)d_in[0];   // [4096, 4096] fp32
    float* out = (float*)d_out;

    int n = in_sizes[0];                 // 16,777,216 floats
    int n4 = n >> 2;                     // 4,194,304 float4s
    int n_tiles = n4 / TILE;             // 2048 exactly
    competitive_sparse_kernel<<<GRID, THREADS>>>(
        (const float4*)features, (float4*)out, n_tiles);
}